// round 16
// baseline (speedup 1.0000x reference)
#include <cuda_runtime.h>
#include <math.h>

#define NPTS     4096
#define NB       16
#define NCLOUD   32
#define NBINS    256
#define IDXMARGIN 128
#define SORT_TPB 512
#define MAIN_TPB 512
#define NSLICE   4
#define WPAIRS   4                           // query-chunk groups per block
#define BLK_PER_PAIR 16
#define MAIN_GRID (NCLOUD * BLK_PER_PAIR)    // 512 blocks

__device__ __align__(16) float4 g_pts[NCLOUD][NPTS];   // sorted (x,y,z,|p|^2)
__device__ int   g_binstart[NCLOUD][NBINS + 1];
__device__ float g_zmin[NCLOUD];
__device__ float g_binw[NCLOUD];
__device__ float g_accum;       // zero at entry/exit of every launch
__device__ unsigned g_count;    // zero at entry/exit of every launch

typedef unsigned long long u64;

static __device__ __forceinline__ u64 bcast2(float v) {
    u64 r;
    asm("mov.b64 %0, {%1, %1};" : "=l"(r) : "f"(v));
    return r;
}
static __device__ __forceinline__ void unpack2(u64 v, float &lo, float &hi) {
    asm("mov.b64 {%0, %1}, %2;" : "=f"(lo), "=f"(hi) : "l"(v));
}
static __device__ __forceinline__ u64 fma2(u64 a, u64 b, u64 c) {
    u64 d;
    asm("fma.rn.f32x2 %0, %1, %2, %3;" : "=l"(d) : "l"(a), "l"(b), "l"(c));
    return d;
}

// ------------- sort kernel: smem-staged z-bucketing of each cloud -----------
__global__ void __launch_bounds__(SORT_TPB) sort_kernel(const float* __restrict__ tpl,
                                                        const float* __restrict__ src) {
    extern __shared__ float stg[];              // [3*NPTS] staged cloud
    __shared__ int hist[NBINS];
    __shared__ int scan_a[NBINS], scan_b[NBINS];
    __shared__ int boff[NBINS + 1];
    __shared__ float rmin[SORT_TPB / 32], rmax[SORT_TPB / 32];
    __shared__ float s_zmin, s_inv;

    const int c = blockIdx.x;
    const float* P = (c < NB) ? (tpl + (size_t)c * NPTS * 3)
                              : (src + (size_t)(c - NB) * NPTS * 3);
    const int tid = threadIdx.x;

    const float4* P4 = (const float4*)P;
    float4* S4 = (float4*)stg;
    for (int i = tid; i < 3 * NPTS / 4; i += SORT_TPB) S4[i] = P4[i];
    if (tid < NBINS) hist[tid] = 0;
    __syncthreads();

    float mn = 3.4e38f, mx = -3.4e38f;
    for (int p = tid; p < NPTS; p += SORT_TPB) {
        float z = stg[3 * p + 2];
        mn = fminf(mn, z);
        mx = fmaxf(mx, z);
    }
#pragma unroll
    for (int o = 16; o; o >>= 1) {
        mn = fminf(mn, __shfl_xor_sync(0xffffffffu, mn, o));
        mx = fmaxf(mx, __shfl_xor_sync(0xffffffffu, mx, o));
    }
    if ((tid & 31) == 0) { rmin[tid >> 5] = mn; rmax[tid >> 5] = mx; }
    __syncthreads();
    if (tid == 0) {
        float zmin = rmin[0], zmax = rmax[0];
        for (int w = 1; w < SORT_TPB / 32; w++) {
            zmin = fminf(zmin, rmin[w]);
            zmax = fmaxf(zmax, rmax[w]);
        }
        float binw = fmaxf((zmax - zmin) / NBINS, 1e-30f);
        s_zmin = zmin;
        s_inv = 1.0f / binw;
        g_zmin[c] = zmin;
        g_binw[c] = binw;
    }
    __syncthreads();
    const float zmin = s_zmin, inv = s_inv;

    for (int p = tid; p < NPTS; p += SORT_TPB) {
        float z = stg[3 * p + 2];
        int bn = min(max((int)((z - zmin) * inv), 0), NBINS - 1);
        atomicAdd(&hist[bn], 1);
    }
    __syncthreads();

    if (tid < NBINS) scan_a[tid] = hist[tid];
    __syncthreads();
    int* cur = scan_a;
    int* nxt = scan_b;
#pragma unroll
    for (int off = 1; off < NBINS; off <<= 1) {
        if (tid < NBINS)
            nxt[tid] = (tid >= off) ? cur[tid] + cur[tid - off] : cur[tid];
        __syncthreads();
        int* t = cur; cur = nxt; nxt = t;
    }
    if (tid < NBINS) boff[tid] = cur[tid] - hist[tid];
    if (tid == 0) boff[NBINS] = NPTS;
    __syncthreads();
    if (tid < NBINS) hist[tid] = 0;
    __syncthreads();

    for (int p = tid; p < NPTS; p += SORT_TPB) {
        float x = stg[3 * p + 0], y = stg[3 * p + 1], z = stg[3 * p + 2];
        int bn = min(max((int)((z - zmin) * inv), 0), NBINS - 1);
        int idx = boff[bn] + atomicAdd(&hist[bn], 1);
        g_pts[c][idx] = make_float4(x, y, z, x * x + y * y + z * z);
    }
    for (int k = tid; k <= NBINS; k += SORT_TPB) g_binstart[c][k] = boff[k];
}

// --- main: smem scan, KQ=2, index margin, 4-way db-slice per query chunk ----
__global__ void __launch_bounds__(MAIN_TPB, 2) chamfer_main(float* __restrict__ out) {
    extern __shared__ float sm[];
    float* sx = sm;
    float* sy = sm + NPTS;
    float* sz = sm + 2 * NPTS;
    float* su = sm + 3 * NPTS;
    int* sbin = (int*)(sm + 4 * NPTS);                 // NBINS+1 ints
    float* pm = (float*)(sbin + NBINS + 1);            // [NSLICE-1][WPAIRS][64]
    float* red = pm + (NSLICE - 1) * WPAIRS * 64;      // 16 floats

    const int tid = threadIdx.x;
    const int b = blockIdx.x;
    const int pair = b >> 4;                  // 0..31
    const int blk  = b & 15;
    const int dir = pair >> 4;
    const int batch = pair & 15;
    const int qcl = (dir == 0) ? batch : NB + batch;
    const int dcl = (dir == 0) ? NB + batch : batch;

    for (int p = tid; p < NPTS; p += MAIN_TPB) {
        float4 v = g_pts[dcl][p];
        sx[p] = v.x; sy[p] = v.y; sz[p] = v.z; su[p] = v.w;
    }
    for (int k = tid; k <= NBINS; k += MAIN_TPB) sbin[k] = g_binstart[dcl][k];
    __syncthreads();

    const float zmin = g_zmin[dcl];
    const float binw = g_binw[dcl];
    const float invw = 1.0f / binw;

    const int warp = tid >> 5, lane = tid & 31;
    const int wpair = warp >> 2;              // 0..3
    const int slice = warp & 3;               // db quad-parity class
    // striped: chunks {blk, blk+16, blk+32, blk+48}, 64 queries each
    const int chunk = wpair * BLK_PER_PAIR + blk;   // 0..63
    const int q0 = chunk * 64 + lane;
    const int q1 = q0 + 32;

    float4 v0 = g_pts[qcl][q0];
    float4 v1 = g_pts[qcl][q1];
    const float qz0 = v0.z, qu0 = v0.w;
    const float qz1 = v1.z, qu1 = v1.w;
    const u64 pqx0 = bcast2(-2.0f * v0.x);
    const u64 pqy0 = bcast2(-2.0f * v0.y);
    const u64 pqz0 = bcast2(-2.0f * qz0);
    const u64 pqx1 = bcast2(-2.0f * v1.x);
    const u64 pqy1 = bcast2(-2.0f * v1.y);
    const u64 pqz1 = bcast2(-2.0f * qz1);

    float wlo = fminf(qz0, qz1), whi = fmaxf(qz0, qz1);
#pragma unroll
    for (int o = 16; o; o >>= 1) {
        wlo = fminf(wlo, __shfl_xor_sync(0xffffffffu, wlo, o));
        whi = fmaxf(whi, __shfl_xor_sync(0xffffffffu, whi, o));
    }
    const int lo = min(max((int)((wlo - zmin) * invw), 0), NBINS - 1);
    const int hi = min(max((int)((whi - zmin) * invw), 0), NBINS - 1);

    float b0A = 3.4e38f, b0B = 3.4e38f, b1A = 3.4e38f, b1B = 3.4e38f;
    const ulonglong2* vx = (const ulonglong2*)sx;
    const ulonglong2* vy = (const ulonglong2*)sy;
    const ulonglong2* vz = (const ulonglong2*)sz;
    const ulonglong2* vu = (const ulonglong2*)su;

    // scan only quads with (j & 3) == slice; the 3 partner warps cover the
    // other classes; union over slices is exact (each slice's radius is
    // conservative: partial min >= true min).
    auto scan = [&](int a, int e) {
        int j0 = a >> 2;
        j0 += (slice - j0) & 3;
        int j1 = (e + 3) >> 2;
        for (int j = j0; j < j1; j += 4) {
            ulonglong2 bx = vx[j], by = vy[j], bz = vz[j], bu = vu[j];
            u64 a01 = fma2(pqz0, bz.x, bu.x);
            a01 = fma2(pqy0, by.x, a01);
            a01 = fma2(pqx0, bx.x, a01);
            u64 a23 = fma2(pqz0, bz.y, bu.y);
            a23 = fma2(pqy0, by.y, a23);
            a23 = fma2(pqx0, bx.y, a23);
            u64 c01 = fma2(pqz1, bz.x, bu.x);
            c01 = fma2(pqy1, by.x, c01);
            c01 = fma2(pqx1, bx.x, c01);
            u64 c23 = fma2(pqz1, bz.y, bu.y);
            c23 = fma2(pqy1, by.y, c23);
            c23 = fma2(pqx1, bx.y, c23);
            float l0, h0, l1, h1;
            unpack2(a01, l0, h0);
            unpack2(a23, l1, h1);
            b0A = fminf(b0A, fminf(l0, l1));
            b0B = fminf(b0B, fminf(h0, h1));
            unpack2(c01, l0, h0);
            unpack2(c23, l1, h1);
            b1A = fminf(b1A, fminf(l0, l1));
            b1B = fminf(b1B, fminf(h0, h1));
        }
    };

    // initial scan: query span + density-adaptive index-space margin
    int a0 = max(sbin[lo] - IDXMARGIN, 0);
    int a1 = min(sbin[hi + 1] + IDXMARGIN, NPTS);
    scan(a0, a1);

    // coverage-based expansion using this slice's (conservative) partial min
    while (true) {
        float m = fmaxf(qu0 + fminf(b0A, b0B), qu1 + fminf(b1A, b1B));
#pragma unroll
        for (int o = 16; o; o >>= 1) m = fmaxf(m, __shfl_xor_sync(0xffffffffu, m, o));
        m = fmaxf(m, 0.0f);
        float r = sqrtf(m) * 1.0001f + 1e-12f;
        int nlo = max(min((int)((wlo - r - zmin) * invw), NBINS - 1), 0);
        int nhi = min(max((int)((whi + r - zmin) * invw), 0), NBINS - 1);
        int need0 = sbin[nlo];
        int need1 = sbin[nhi + 1];
        bool growL = need0 < a0, growR = need1 > a1;
        if (!growL && !growR) break;
        if (growL) { scan(need0, a0); a0 = need0; }
        if (growR) { scan(a1, need1); a1 = need1; }
    }

    // slices 1..3 publish partial mins; slice 0 combines
    if (slice != 0) {
        int base = (slice - 1) * WPAIRS * 64 + wpair * 64;
        pm[base + lane]      = fminf(b0A, b0B);
        pm[base + 32 + lane] = fminf(b1A, b1B);
    }
    __syncthreads();

    float s = 0.0f;
    if (slice == 0) {
        float m0 = fminf(b0A, b0B);
        float m1 = fminf(b1A, b1B);
#pragma unroll
        for (int sl = 0; sl < NSLICE - 1; sl++) {
            int base = sl * WPAIRS * 64 + wpair * 64;
            m0 = fminf(m0, pm[base + lane]);
            m1 = fminf(m1, pm[base + 32 + lane]);
        }
        s = sqrtf(fmaxf(qu0 + m0, 0.0f)) + sqrtf(fmaxf(qu1 + m1, 0.0f));
    }

    // block reduction (16 warps; non-zero only from slice-0 warps)
#pragma unroll
    for (int o = 16; o; o >>= 1) s += __shfl_xor_sync(0xffffffffu, s, o);
    if (lane == 0) red[warp] = s;
    __syncthreads();
    if (tid == 0) {
        float t = 0.0f;
#pragma unroll
        for (int w = 0; w < MAIN_TPB / 32; w++) t += red[w];
        atomicAdd(&g_accum, t);
        __threadfence();
        unsigned old = atomicAdd(&g_count, 1u);
        if (old == MAIN_GRID - 1) {
            __threadfence();
            float total = atomicAdd(&g_accum, 0.0f);
            out[0] = total * (1.0f / 131072.0f);   // / (2*16*4096)
            g_accum = 0.0f;
            __threadfence();
            atomicExch(&g_count, 0u);
        }
    }
}

extern "C" void kernel_launch(void* const* d_in, const int* in_sizes, int n_in,
                              void* d_out, int out_size) {
    const float* tpl = (const float*)d_in[0];
    const float* src = (const float*)d_in[1];
    (void)in_sizes; (void)n_in; (void)out_size;

    const int sort_smem = 3 * NPTS * (int)sizeof(float);
    cudaFuncSetAttribute(sort_kernel, cudaFuncAttributeMaxDynamicSharedMemorySize, sort_smem);

    const int main_smem = 4 * NPTS * (int)sizeof(float)
                        + (NBINS + 1) * (int)sizeof(int)
                        + ((NSLICE - 1) * WPAIRS * 64 + MAIN_TPB / 32) * (int)sizeof(float);
    cudaFuncSetAttribute(chamfer_main, cudaFuncAttributeMaxDynamicSharedMemorySize, main_smem);

    sort_kernel<<<NCLOUD, SORT_TPB, sort_smem>>>(tpl, src);
    chamfer_main<<<MAIN_GRID, MAIN_TPB, main_smem>>>((float*)d_out);
}

// round 17
// speedup vs baseline: 1.2473x; 1.2473x over previous
#include <cuda_runtime.h>
#include <math.h>

#define NPTS     4096
#define NB       16
#define NCLOUD   32
#define NBINS    256
#define IDXMARGIN 128
#define SORT_TPB 512
#define MAIN_TPB 512
#define NSLICE   4
#define WPAIRS   4
#define BLK_PER_PAIR 16
#define MAIN_GRID (NCLOUD * BLK_PER_PAIR)    // 512 blocks

__device__ __align__(16) float4 g_pts[NCLOUD][NPTS];   // sorted (x,y,z,|p|^2)
__device__ int   g_binstart[NCLOUD][NBINS + 1];
__device__ float g_zmin[NCLOUD];
__device__ float g_binw[NCLOUD];
__device__ float g_accum;       // zero at entry/exit of every launch
__device__ unsigned g_count;    // zero at entry/exit of every launch

typedef unsigned long long u64;

static __device__ __forceinline__ u64 bcast2(float v) {
    u64 r;
    asm("mov.b64 %0, {%1, %1};" : "=l"(r) : "f"(v));
    return r;
}
static __device__ __forceinline__ void unpack2(u64 v, float &lo, float &hi) {
    asm("mov.b64 {%0, %1}, %2;" : "=f"(lo), "=f"(hi) : "l"(v));
}
static __device__ __forceinline__ u64 fma2(u64 a, u64 b, u64 c) {
    u64 d;
    asm("fma.rn.f32x2 %0, %1, %2, %3;" : "=l"(d) : "l"(a), "l"(b), "l"(c));
    return d;
}

// ------------- sort kernel: smem-staged z-bucketing of each cloud -----------
__global__ void __launch_bounds__(SORT_TPB) sort_kernel(const float* __restrict__ tpl,
                                                        const float* __restrict__ src) {
    extern __shared__ float stg[];              // [3*NPTS] staged cloud
    __shared__ int hist[NBINS];
    __shared__ int scan_a[NBINS], scan_b[NBINS];
    __shared__ int boff[NBINS + 1];
    __shared__ float rmin[SORT_TPB / 32], rmax[SORT_TPB / 32];
    __shared__ float s_zmin, s_inv;

    const int c = blockIdx.x;
    const float* P = (c < NB) ? (tpl + (size_t)c * NPTS * 3)
                              : (src + (size_t)(c - NB) * NPTS * 3);
    const int tid = threadIdx.x;

    const float4* P4 = (const float4*)P;
    float4* S4 = (float4*)stg;
    for (int i = tid; i < 3 * NPTS / 4; i += SORT_TPB) S4[i] = P4[i];
    if (tid < NBINS) hist[tid] = 0;
    __syncthreads();

    float mn = 3.4e38f, mx = -3.4e38f;
    for (int p = tid; p < NPTS; p += SORT_TPB) {
        float z = stg[3 * p + 2];
        mn = fminf(mn, z);
        mx = fmaxf(mx, z);
    }
#pragma unroll
    for (int o = 16; o; o >>= 1) {
        mn = fminf(mn, __shfl_xor_sync(0xffffffffu, mn, o));
        mx = fmaxf(mx, __shfl_xor_sync(0xffffffffu, mx, o));
    }
    if ((tid & 31) == 0) { rmin[tid >> 5] = mn; rmax[tid >> 5] = mx; }
    __syncthreads();
    if (tid == 0) {
        float zmin = rmin[0], zmax = rmax[0];
        for (int w = 1; w < SORT_TPB / 32; w++) {
            zmin = fminf(zmin, rmin[w]);
            zmax = fmaxf(zmax, rmax[w]);
        }
        float binw = fmaxf((zmax - zmin) / NBINS, 1e-30f);
        s_zmin = zmin;
        s_inv = 1.0f / binw;
        g_zmin[c] = zmin;
        g_binw[c] = binw;
    }
    __syncthreads();
    const float zmin = s_zmin, inv = s_inv;

    for (int p = tid; p < NPTS; p += SORT_TPB) {
        float z = stg[3 * p + 2];
        int bn = min(max((int)((z - zmin) * inv), 0), NBINS - 1);
        atomicAdd(&hist[bn], 1);
    }
    __syncthreads();

    if (tid < NBINS) scan_a[tid] = hist[tid];
    __syncthreads();
    int* cur = scan_a;
    int* nxt = scan_b;
#pragma unroll
    for (int off = 1; off < NBINS; off <<= 1) {
        if (tid < NBINS)
            nxt[tid] = (tid >= off) ? cur[tid] + cur[tid - off] : cur[tid];
        __syncthreads();
        int* t = cur; cur = nxt; nxt = t;
    }
    if (tid < NBINS) boff[tid] = cur[tid] - hist[tid];
    if (tid == 0) boff[NBINS] = NPTS;
    __syncthreads();
    if (tid < NBINS) hist[tid] = 0;
    __syncthreads();

    for (int p = tid; p < NPTS; p += SORT_TPB) {
        float x = stg[3 * p + 0], y = stg[3 * p + 1], z = stg[3 * p + 2];
        int bn = min(max((int)((z - zmin) * inv), 0), NBINS - 1);
        int idx = boff[bn] + atomicAdd(&hist[bn], 1);
        g_pts[c][idx] = make_float4(x, y, z, x * x + y * y + z * z);
    }
    for (int k = tid; k <= NBINS; k += SORT_TPB) g_binstart[c][k] = boff[k];
}

// --- main: 4-way db-slice with slice-cooperative (true-min) expansion -------
__global__ void __launch_bounds__(MAIN_TPB, 2) chamfer_main(float* __restrict__ out) {
    extern __shared__ float sm[];
    float* sx = sm;
    float* sy = sm + NPTS;
    float* sz = sm + 2 * NPTS;
    float* su = sm + 3 * NPTS;
    int* sbin = (int*)(sm + 4 * NPTS);                 // NBINS+1 ints
    float* pm = (float*)(sbin + NBINS + 1);            // [NSLICE][WPAIRS][64]
    float* red = pm + NSLICE * WPAIRS * 64;            // 16 floats

    const int tid = threadIdx.x;
    const int b = blockIdx.x;
    const int pair = b >> 4;                  // 0..31
    const int blk  = b & 15;
    const int dir = pair >> 4;
    const int batch = pair & 15;
    const int qcl = (dir == 0) ? batch : NB + batch;
    const int dcl = (dir == 0) ? NB + batch : batch;

    for (int p = tid; p < NPTS; p += MAIN_TPB) {
        float4 v = g_pts[dcl][p];
        sx[p] = v.x; sy[p] = v.y; sz[p] = v.z; su[p] = v.w;
    }
    for (int k = tid; k <= NBINS; k += MAIN_TPB) sbin[k] = g_binstart[dcl][k];
    __syncthreads();

    const float zmin = g_zmin[dcl];
    const float binw = g_binw[dcl];
    const float invw = 1.0f / binw;

    const int warp = tid >> 5, lane = tid & 31;
    const int wpair = warp >> 2;              // 0..3
    const int slice = warp & 3;               // db quad-parity class
    const int chunk = wpair * BLK_PER_PAIR + blk;   // 0..63 (striped)
    const int q0 = chunk * 64 + lane;
    const int q1 = q0 + 32;

    float4 v0 = g_pts[qcl][q0];
    float4 v1 = g_pts[qcl][q1];
    const float qz0 = v0.z, qu0 = v0.w;
    const float qz1 = v1.z, qu1 = v1.w;
    const u64 pqx0 = bcast2(-2.0f * v0.x);
    const u64 pqy0 = bcast2(-2.0f * v0.y);
    const u64 pqz0 = bcast2(-2.0f * qz0);
    const u64 pqx1 = bcast2(-2.0f * v1.x);
    const u64 pqy1 = bcast2(-2.0f * v1.y);
    const u64 pqz1 = bcast2(-2.0f * qz1);

    float wlo = fminf(qz0, qz1), whi = fmaxf(qz0, qz1);
#pragma unroll
    for (int o = 16; o; o >>= 1) {
        wlo = fminf(wlo, __shfl_xor_sync(0xffffffffu, wlo, o));
        whi = fmaxf(whi, __shfl_xor_sync(0xffffffffu, whi, o));
    }
    const int lo = min(max((int)((wlo - zmin) * invw), 0), NBINS - 1);
    const int hi = min(max((int)((whi - zmin) * invw), 0), NBINS - 1);

    float b0A = 3.4e38f, b0B = 3.4e38f, b1A = 3.4e38f, b1B = 3.4e38f;
    const ulonglong2* vx = (const ulonglong2*)sx;
    const ulonglong2* vy = (const ulonglong2*)sy;
    const ulonglong2* vz = (const ulonglong2*)sz;
    const ulonglong2* vu = (const ulonglong2*)su;

    // scan only quads with (j & 3) == slice; union over the 4 slices is exact.
    auto scan = [&](int a, int e) {
        int j0 = a >> 2;
        j0 += (slice - j0) & 3;
        int j1 = (e + 3) >> 2;
        for (int j = j0; j < j1; j += 4) {
            ulonglong2 bx = vx[j], by = vy[j], bz = vz[j], bu = vu[j];
            u64 a01 = fma2(pqz0, bz.x, bu.x);
            a01 = fma2(pqy0, by.x, a01);
            a01 = fma2(pqx0, bx.x, a01);
            u64 a23 = fma2(pqz0, bz.y, bu.y);
            a23 = fma2(pqy0, by.y, a23);
            a23 = fma2(pqx0, bx.y, a23);
            u64 c01 = fma2(pqz1, bz.x, bu.x);
            c01 = fma2(pqy1, by.x, c01);
            c01 = fma2(pqx1, bx.x, c01);
            u64 c23 = fma2(pqz1, bz.y, bu.y);
            c23 = fma2(pqy1, by.y, c23);
            c23 = fma2(pqx1, bx.y, c23);
            float l0, h0, l1, h1;
            unpack2(a01, l0, h0);
            unpack2(a23, l1, h1);
            b0A = fminf(b0A, fminf(l0, l1));
            b0B = fminf(b0B, fminf(h0, h1));
            unpack2(c01, l0, h0);
            unpack2(c23, l1, h1);
            b1A = fminf(b1A, fminf(l0, l1));
            b1B = fminf(b1B, fminf(h0, h1));
        }
    };

    // initial scan: query span + density-adaptive index-space margin
    int a0 = max(sbin[lo] - IDXMARGIN, 0);
    int a1 = min(sbin[hi + 1] + IDXMARGIN, NPTS);
    scan(a0, a1);

    // slice-cooperative expansion: publish partial mins, combine across slices
    // (TRUE per-query min -> no radius inflation), block-uniform loop.
    const int pmbase = wpair * 64;
    float m0f = 3.4e38f, m1f = 3.4e38f;
    while (true) {
        pm[(slice * WPAIRS) * 64 + pmbase + lane]      = fminf(b0A, b0B);
        pm[(slice * WPAIRS) * 64 + pmbase + 32 + lane] = fminf(b1A, b1B);
        __syncthreads();
        float m0 = 3.4e38f, m1 = 3.4e38f;
#pragma unroll
        for (int s = 0; s < NSLICE; s++) {
            m0 = fminf(m0, pm[(s * WPAIRS) * 64 + pmbase + lane]);
            m1 = fminf(m1, pm[(s * WPAIRS) * 64 + pmbase + 32 + lane]);
        }
        m0f = m0; m1f = m1;
        float m = fmaxf(qu0 + m0, qu1 + m1);
#pragma unroll
        for (int o = 16; o; o >>= 1) m = fmaxf(m, __shfl_xor_sync(0xffffffffu, m, o));
        m = fmaxf(m, 0.0f);
        float r = sqrtf(m) * 1.0001f + 1e-12f;
        int nlo = max(min((int)((wlo - r - zmin) * invw), NBINS - 1), 0);
        int nhi = min(max((int)((whi + r - zmin) * invw), 0), NBINS - 1);
        int need0 = sbin[nlo];
        int need1 = sbin[nhi + 1];
        bool grow = (need0 < a0) || (need1 > a1);
        if (!__syncthreads_or(grow)) break;     // also fences pm for next round
        if (need0 < a0) { scan(need0, a0); a0 = need0; }
        if (need1 > a1) { scan(a1, need1); a1 = need1; }
    }

    // at loop exit m0f/m1f hold the final combined mins (no growth round)
    float s = 0.0f;
    if (slice == 0)
        s = sqrtf(fmaxf(qu0 + m0f, 0.0f)) + sqrtf(fmaxf(qu1 + m1f, 0.0f));

    // block reduction (16 warps; non-zero only from slice-0 warps)
#pragma unroll
    for (int o = 16; o; o >>= 1) s += __shfl_xor_sync(0xffffffffu, s, o);
    if (lane == 0) red[warp] = s;
    __syncthreads();
    if (tid == 0) {
        float t = 0.0f;
#pragma unroll
        for (int w = 0; w < MAIN_TPB / 32; w++) t += red[w];
        atomicAdd(&g_accum, t);
        __threadfence();
        unsigned old = atomicAdd(&g_count, 1u);
        if (old == MAIN_GRID - 1) {
            __threadfence();
            float total = atomicAdd(&g_accum, 0.0f);
            out[0] = total * (1.0f / 131072.0f);   // / (2*16*4096)
            g_accum = 0.0f;
            __threadfence();
            atomicExch(&g_count, 0u);
        }
    }
}

extern "C" void kernel_launch(void* const* d_in, const int* in_sizes, int n_in,
                              void* d_out, int out_size) {
    const float* tpl = (const float*)d_in[0];
    const float* src = (const float*)d_in[1];
    (void)in_sizes; (void)n_in; (void)out_size;

    const int sort_smem = 3 * NPTS * (int)sizeof(float);
    cudaFuncSetAttribute(sort_kernel, cudaFuncAttributeMaxDynamicSharedMemorySize, sort_smem);

    const int main_smem = 4 * NPTS * (int)sizeof(float)
                        + (NBINS + 1) * (int)sizeof(int)
                        + (NSLICE * WPAIRS * 64 + MAIN_TPB / 32) * (int)sizeof(float);
    cudaFuncSetAttribute(chamfer_main, cudaFuncAttributeMaxDynamicSharedMemorySize, main_smem);

    sort_kernel<<<NCLOUD, SORT_TPB, sort_smem>>>(tpl, src);
    chamfer_main<<<MAIN_GRID, MAIN_TPB, main_smem>>>((float*)d_out);
}